// round 5
// baseline (speedup 1.0000x reference)
#include <cuda_runtime.h>
#include <cstdint>
#include <cstddef>

// Problem constants
#define B_  2
#define N_  2048
#define D_  1024
#define H_  16
#define DP_ 64
#define EQ_ 3072            // 3*H*DP
#define M_ROWS 4096         // B*N

// Scratch (no allocations allowed)
__device__ float g_qkv [(size_t)M_ROWS * EQ_];   // 48 MB (tf32-rounded)
__device__ float g_attn[(size_t)M_ROWS * D_];    // 16 MB (tf32-rounded)
__device__ float g_xr  [(size_t)M_ROWS * D_];    // 16 MB x, tf32-rounded
__device__ float g_wq  [(size_t)D_ * EQ_];       // 12 MB W_qkv, tf32-rounded
__device__ float g_wo  [(size_t)D_ * D_];        //  4 MB W_out, tf32-rounded

// ---------------------------------------------------------------------------
// Helpers
// ---------------------------------------------------------------------------
__device__ __forceinline__ uint32_t smem_u32(const void* p) {
    uint32_t a;
    asm("{ .reg .u64 t; cvta.to.shared.u64 t, %1; cvt.u32.u64 %0, t; }"
        : "=r"(a) : "l"(p));
    return a;
}

__device__ __forceinline__ uint32_t f2tf(float x) {
    uint32_t r;
    asm("cvt.rna.tf32.f32 %0, %1;" : "=r"(r) : "f"(x));
    return r;
}

__device__ __forceinline__ void cp16(uint32_t dst, const float* src) {
    asm volatile("cp.async.cg.shared.global [%0], [%1], 16;"
                 :: "r"(dst), "l"(__cvta_generic_to_global(src)));
}
#define CP_COMMIT asm volatile("cp.async.commit_group;" ::: "memory")
#define CP_WAIT0  asm volatile("cp.async.wait_group 0;" ::: "memory")
#define CP_WAIT1  asm volatile("cp.async.wait_group 1;" ::: "memory")

// D += A(16x8 tf32, row) * B(8x8 tf32, col)
__device__ __forceinline__ void mma8(float d[4], const uint32_t a[4], const uint32_t b[2]) {
    asm volatile(
        "mma.sync.aligned.m16n8k8.row.col.f32.tf32.tf32.f32 "
        "{%0,%1,%2,%3}, {%4,%5,%6,%7}, {%8,%9}, {%0,%1,%2,%3};"
        : "+f"(d[0]), "+f"(d[1]), "+f"(d[2]), "+f"(d[3])
        : "r"(a[0]), "r"(a[1]), "r"(a[2]), "r"(a[3]), "r"(b[0]), "r"(b[1]));
}

// ---------------------------------------------------------------------------
// Pre-round f32 -> tf32 bit patterns (elementwise, float4)
// ---------------------------------------------------------------------------
__global__ __launch_bounds__(256) void round_tf32_kernel(
    const float4* __restrict__ in, float4* __restrict__ out, int n4)
{
    int i = blockIdx.x * blockDim.x + threadIdx.x;
    if (i >= n4) return;
    float4 v = in[i];
    uint4 u;
    u.x = f2tf(v.x); u.y = f2tf(v.y); u.z = f2tf(v.z); u.w = f2tf(v.w);
    *(uint4*)&out[i] = u;
}

// ---------------------------------------------------------------------------
// GEMM: C[M,Nn] = A[M,K] @ B[K,Nn] + bias (row-major, operands pre-tf32)
// CTA 128x128, KC=32, 8 warps (2x4) of 64x32, 3-stage cp.async, 1 sync/chunk.
// smem stages: A [128][36] f32 (18432B), B [32][136] f32 (17408B)
// ---------------------------------------------------------------------------
#define AST 4608   // A stage stride in words
#define BST 4352   // B stage stride in words
#define GEMM_SMEM (3*18432 + 3*17408)

template<bool ROUND_OUT>
__global__ __launch_bounds__(256, 2) void gemm_tc(
    const float* __restrict__ A, const float* __restrict__ Bw,
    const float* __restrict__ bias, float* __restrict__ C,
    int M, int Nn, int K)
{
    extern __shared__ char smem[];
    const uint32_t sA0 = smem_u32(smem);
    const uint32_t sB0 = sA0 + 3 * 18432;
    const uint32_t* uA = (const uint32_t*)smem;
    const uint32_t* uB = (const uint32_t*)(smem + 3 * 18432);

    const int tid = threadIdx.x;
    const int wid = tid >> 5, lane = tid & 31;
    const int gid = lane >> 2, tig = lane & 3;
    const int wm = wid >> 2, wn = wid & 3;
    const int m0 = blockIdx.y * 128, n0 = blockIdx.x * 128;

    float acc[4][4][4];
#pragma unroll
    for (int i = 0; i < 4; i++)
#pragma unroll
        for (int j = 0; j < 4; j++)
#pragma unroll
            for (int r = 0; r < 4; r++) acc[i][j][r] = 0.f;

    auto load_chunk = [&](int k0, int s) {
        const uint32_t da = sA0 + s * (AST * 4);
        const uint32_t db = sB0 + s * (BST * 4);
#pragma unroll
        for (int p = 0; p < 4; p++) {
            int idx = tid + p * 256;
            int m = idx >> 3, k4 = (idx & 7) * 4;
            cp16(da + (m * 36 + k4) * 4, A + (size_t)(m0 + m) * K + k0 + k4);
        }
#pragma unroll
        for (int p = 0; p < 4; p++) {
            int idx = tid + p * 256;
            int kr = idx >> 5, n4 = (idx & 31) * 4;
            cp16(db + (kr * 136 + n4) * 4, Bw + (size_t)(k0 + kr) * Nn + n0 + n4);
        }
        CP_COMMIT;
    };

    const int nch = K >> 5;
    load_chunk(0, 0);
    if (nch > 1) load_chunk(32, 1);

    int stage = 0;
    for (int c = 0; c < nch; c++) {
        if (c + 1 < nch) { CP_WAIT1; } else { CP_WAIT0; }
        __syncthreads();
        if (c + 2 < nch) {
            int s2 = stage + 2; if (s2 >= 3) s2 -= 3;
            load_chunk((c + 2) * 32, s2);
        }

        const uint32_t* cA = uA + stage * AST;
        const uint32_t* cB = uB + stage * BST;

#pragma unroll
        for (int kk = 0; kk < 4; kk++) {
            const int k = kk * 8;
            uint32_t af[4][4], bf[4][2];
#pragma unroll
            for (int mt = 0; mt < 4; mt++) {
                const uint32_t* pr = cA + (wm * 64 + mt * 16 + gid) * 36 + k + tig;
                af[mt][0] = pr[0];
                af[mt][1] = pr[8 * 36];
                af[mt][2] = pr[4];
                af[mt][3] = pr[8 * 36 + 4];
            }
#pragma unroll
            for (int nt = 0; nt < 4; nt++) {
                const uint32_t* pc = cB + (k + tig) * 136 + wn * 32 + nt * 8 + gid;
                bf[nt][0] = pc[0];
                bf[nt][1] = pc[4 * 136];
            }
#pragma unroll
            for (int mt = 0; mt < 4; mt++)
#pragma unroll
                for (int nt = 0; nt < 4; nt++)
                    mma8(acc[mt][nt], af[mt], bf[nt]);
        }
        stage++; if (stage >= 3) stage -= 3;
    }

    // epilogue
#pragma unroll
    for (int mt = 0; mt < 4; mt++) {
        const int row = m0 + wm * 64 + mt * 16 + gid;
#pragma unroll
        for (int nt = 0; nt < 4; nt++) {
            const int col = n0 + wn * 32 + nt * 8 + 2 * tig;
            float2 bv = *(const float2*)(bias + col);
            float v00 = acc[mt][nt][0] + bv.x, v01 = acc[mt][nt][1] + bv.y;
            float v10 = acc[mt][nt][2] + bv.x, v11 = acc[mt][nt][3] + bv.y;
            if (ROUND_OUT) {
                uint2 u0; u0.x = f2tf(v00); u0.y = f2tf(v01);
                uint2 u1; u1.x = f2tf(v10); u1.y = f2tf(v11);
                *(uint2*)(C + (size_t)row * Nn + col) = u0;
                *(uint2*)(C + (size_t)(row + 8) * Nn + col) = u1;
            } else {
                float2 o0; o0.x = v00; o0.y = v01;
                float2 o1; o1.x = v10; o1.y = v11;
                *(float2*)(C + (size_t)row * Nn + col) = o0;
                *(float2*)(C + (size_t)(row + 8) * Nn + col) = o1;
            }
        }
    }
}

// ---------------------------------------------------------------------------
// Flash attention (tf32 mma.sync, pre-rounded qkv): CTA = (b,h,128-q tile),
// 8 warps x 16 query rows. K/V 3-stage cp.async, 1 sync/tile.
// smem: QP [128][68] @0 | K 3x[64][68] | V 3x[64][72]
// ---------------------------------------------------------------------------
#define KST 4352   // K stage words
#define VST 4608   // V stage words
#define FLASH_SMEM (34816 + 3*17408 + 3*18432)

__global__ __launch_bounds__(256) void flash_tc(
    const float* __restrict__ qkv, float* __restrict__ attn)
{
    extern __shared__ char smem[];
    uint32_t* uQP = (uint32_t*)smem;
    const uint32_t* uK = (const uint32_t*)(smem + 34816);
    const uint32_t* uV = (const uint32_t*)(smem + 34816 + 3 * 17408);
    const uint32_t sQP = smem_u32(smem);
    const uint32_t sK  = sQP + 34816;
    const uint32_t sV  = sK + 3 * 17408;

    const int tid = threadIdx.x, wid = tid >> 5, lane = tid & 31;
    const int gid = lane >> 2, tig = lane & 3;
    const int qt = blockIdx.x, h = blockIdx.y, b = blockIdx.z;
    const size_t rowbase = (size_t)(b * N_) * EQ_ + h * 192;
    const int q0 = qt * 128;

    auto load_kv = [&](int t, int s) {
#pragma unroll
        for (int p = 0; p < 4; p++) {
            int idx = tid + p * 256;
            int r = idx >> 4, c4 = (idx & 15) * 4;
            const float* g = qkv + rowbase + (size_t)(t * 64 + r) * EQ_;
            cp16(sK + s * 17408 + (r * 68 + c4) * 4, g + 64 + c4);
            cp16(sV + s * 18432 + (r * 72 + c4) * 4, g + 128 + c4);
        }
        CP_COMMIT;
    };

    // prologue: Q shares commit group with KV tile 0
#pragma unroll
    for (int p = 0; p < 8; p++) {
        int idx = tid + p * 256;
        int r = idx >> 4, c4 = (idx & 15) * 4;
        cp16(sQP + (r * 68 + c4) * 4, qkv + rowbase + (size_t)(q0 + r) * EQ_ + c4);
    }
    load_kv(0, 0);
    load_kv(1, 1);

    uint32_t qf[8][4];
    float o[8][4];
#pragma unroll
    for (int nt = 0; nt < 8; nt++)
#pragma unroll
        for (int r = 0; r < 4; r++) o[nt][r] = 0.f;
    float m0r = -1e30f, m1r = -1e30f, l0r = 0.f, l1r = 0.f;

    const int T = N_ / 64;
    int stage = 0;
    for (int t = 0; t < T; t++) {
        if (t + 1 < T) { CP_WAIT1; } else { CP_WAIT0; }
        __syncthreads();
        if (t + 2 < T) {
            int s2 = stage + 2; if (s2 >= 3) s2 -= 3;
            load_kv(t + 2, s2);
        }

        if (t == 0) {
            // persistent Q fragments (pre-rounded tf32 bits; *0.125 keeps tf32)
#pragma unroll
            for (int kk = 0; kk < 8; kk++) {
                const uint32_t* pr = uQP + (wid * 16 + gid) * 68 + kk * 8 + tig;
                qf[kk][0] = __float_as_uint(__uint_as_float(pr[0]) * 0.125f);
                qf[kk][1] = __float_as_uint(__uint_as_float(pr[8 * 68]) * 0.125f);
                qf[kk][2] = __float_as_uint(__uint_as_float(pr[4]) * 0.125f);
                qf[kk][3] = __float_as_uint(__uint_as_float(pr[8 * 68 + 4]) * 0.125f);
            }
        }
        const uint32_t* cK = uK + stage * KST;
        const uint32_t* cV = uV + stage * VST;
        stage++; if (stage >= 3) stage -= 3;

        // S = Q @ K^T (warp: 16 x 64)
        float sc[8][4];
#pragma unroll
        for (int nt = 0; nt < 8; nt++)
#pragma unroll
            for (int r = 0; r < 4; r++) sc[nt][r] = 0.f;
#pragma unroll
        for (int kk = 0; kk < 8; kk++) {
#pragma unroll
            for (int nt = 0; nt < 8; nt++) {
                uint32_t bf[2];
                const uint32_t* pc = cK + (nt * 8 + gid) * 68 + kk * 8 + tig;
                bf[0] = pc[0];
                bf[1] = pc[4];
                mma8(sc[nt], qf[kk], bf);
            }
        }

        // online softmax (rows gid, gid+8; reduce over 4-lane quad)
        float mx0 = sc[0][0], mx1 = sc[0][2];
#pragma unroll
        for (int nt = 0; nt < 8; nt++) {
            mx0 = fmaxf(mx0, fmaxf(sc[nt][0], sc[nt][1]));
            mx1 = fmaxf(mx1, fmaxf(sc[nt][2], sc[nt][3]));
        }
        mx0 = fmaxf(mx0, __shfl_xor_sync(0xffffffffu, mx0, 1));
        mx0 = fmaxf(mx0, __shfl_xor_sync(0xffffffffu, mx0, 2));
        mx1 = fmaxf(mx1, __shfl_xor_sync(0xffffffffu, mx1, 1));
        mx1 = fmaxf(mx1, __shfl_xor_sync(0xffffffffu, mx1, 2));

        const float mn0 = fmaxf(m0r, mx0), mn1 = fmaxf(m1r, mx1);
        const float scl0 = __expf(m0r - mn0), scl1 = __expf(m1r - mn1);
        m0r = mn0; m1r = mn1;

        float sum0 = 0.f, sum1 = 0.f;
#pragma unroll
        for (int nt = 0; nt < 8; nt++) {
            sc[nt][0] = __expf(sc[nt][0] - mn0); sum0 += sc[nt][0];
            sc[nt][1] = __expf(sc[nt][1] - mn0); sum0 += sc[nt][1];
            sc[nt][2] = __expf(sc[nt][2] - mn1); sum1 += sc[nt][2];
            sc[nt][3] = __expf(sc[nt][3] - mn1); sum1 += sc[nt][3];
        }
        l0r = l0r * scl0 + sum0;
        l1r = l1r * scl1 + sum1;
#pragma unroll
        for (int nt = 0; nt < 8; nt++) {
            o[nt][0] *= scl0; o[nt][1] *= scl0;
            o[nt][2] *= scl1; o[nt][3] *= scl1;
        }

        // write P (tf32) into QP region (warp-private rows)
        uint32_t* pb0 = uQP + (wid * 16 + gid) * 68 + 2 * tig;
        uint32_t* pb1 = uQP + (wid * 16 + gid + 8) * 68 + 2 * tig;
#pragma unroll
        for (int nt = 0; nt < 8; nt++) {
            uint2 u0; u0.x = f2tf(sc[nt][0]); u0.y = f2tf(sc[nt][1]);
            uint2 u1; u1.x = f2tf(sc[nt][2]); u1.y = f2tf(sc[nt][3]);
            *(uint2*)(pb0 + nt * 8) = u0;
            *(uint2*)(pb1 + nt * 8) = u1;
        }
        __syncwarp();

        // O += P @ V
#pragma unroll
        for (int kk = 0; kk < 8; kk++) {
            uint32_t af[4];
            const uint32_t* pp = uQP + (wid * 16 + gid) * 68 + kk * 8 + tig;
            af[0] = pp[0];
            af[1] = pp[8 * 68];
            af[2] = pp[4];
            af[3] = pp[8 * 68 + 4];
#pragma unroll
            for (int nt = 0; nt < 8; nt++) {
                uint32_t bf[2];
                const uint32_t* pv = cV + (kk * 8 + tig) * 72 + nt * 8 + gid;
                bf[0] = pv[0];
                bf[1] = pv[4 * 72];
                mma8(o[nt], af, bf);
            }
        }
    }

    // finalize (write tf32-rounded so gemm3 loads raw bits)
    l0r += __shfl_xor_sync(0xffffffffu, l0r, 1);
    l0r += __shfl_xor_sync(0xffffffffu, l0r, 2);
    l1r += __shfl_xor_sync(0xffffffffu, l1r, 1);
    l1r += __shfl_xor_sync(0xffffffffu, l1r, 2);
    const float inv0 = 1.0f / l0r, inv1 = 1.0f / l1r;

    const int q = b * N_ + q0 + wid * 16 + gid;
    uint32_t* or0 = (uint32_t*)attn + (size_t)q * D_ + h * 64 + 2 * tig;
    uint32_t* or1 = (uint32_t*)attn + (size_t)(q + 8) * D_ + h * 64 + 2 * tig;
#pragma unroll
    for (int nt = 0; nt < 8; nt++) {
        uint2 v0; v0.x = f2tf(o[nt][0] * inv0); v0.y = f2tf(o[nt][1] * inv0);
        uint2 v1; v1.x = f2tf(o[nt][2] * inv1); v1.y = f2tf(o[nt][3] * inv1);
        *(uint2*)(or0 + nt * 8) = v0;
        *(uint2*)(or1 + nt * 8) = v1;
    }
}

// ---------------------------------------------------------------------------
// Launch
// ---------------------------------------------------------------------------
extern "C" void kernel_launch(void* const* d_in, const int* in_sizes, int n_in,
                              void* d_out, int out_size)
{
    const float* x     = (const float*)d_in[0];
    const float* W_qkv = (const float*)d_in[1];
    const float* b_qkv = (const float*)d_in[2];
    const float* W_out = (const float*)d_in[3];
    const float* b_out = (const float*)d_in[4];
    float* out = (float*)d_out;

    float *qkv, *attn, *xr, *wq, *wo;
    cudaGetSymbolAddress((void**)&qkv,  g_qkv);
    cudaGetSymbolAddress((void**)&attn, g_attn);
    cudaGetSymbolAddress((void**)&xr,   g_xr);
    cudaGetSymbolAddress((void**)&wq,   g_wq);
    cudaGetSymbolAddress((void**)&wo,   g_wo);

    cudaFuncSetAttribute(gemm_tc<true>,  cudaFuncAttributeMaxDynamicSharedMemorySize, GEMM_SMEM);
    cudaFuncSetAttribute(gemm_tc<false>, cudaFuncAttributeMaxDynamicSharedMemorySize, GEMM_SMEM);
    cudaFuncSetAttribute(flash_tc, cudaFuncAttributeMaxDynamicSharedMemorySize, FLASH_SMEM);

    // 0) pre-round operands to tf32 bit patterns
    {
        int n4;
        n4 = (M_ROWS * D_) / 4;
        round_tf32_kernel<<<(n4 + 255) / 256, 256>>>((const float4*)x, (float4*)xr, n4);
        n4 = (D_ * EQ_) / 4;
        round_tf32_kernel<<<(n4 + 255) / 256, 256>>>((const float4*)W_qkv, (float4*)wq, n4);
        n4 = (D_ * D_) / 4;
        round_tf32_kernel<<<(n4 + 255) / 256, 256>>>((const float4*)W_out, (float4*)wo, n4);
    }

    // 1) QKV projection (output tf32-rounded for flash)
    gemm_tc<true><<<dim3(EQ_ / 128, M_ROWS / 128), 256, GEMM_SMEM>>>(
        xr, wq, b_qkv, qkv, M_ROWS, EQ_, D_);

    // 2) fused flash attention -> attn (tf32-rounded)
    flash_tc<<<dim3(N_ / 128, H_, B_), 256, FLASH_SMEM>>>(qkv, attn);

    // 3) output projection (full f32 out)
    gemm_tc<false><<<dim3(D_ / 128, M_ROWS / 128), 256, GEMM_SMEM>>>(
        attn, wo, b_out, out, M_ROWS, D_, D_);
}

// round 6
// speedup vs baseline: 1.0849x; 1.0849x over previous
#include <cuda_runtime.h>
#include <cstdint>
#include <cstddef>

// Problem constants
#define B_  2
#define N_  2048
#define D_  1024
#define H_  16
#define DP_ 64
#define EQ_ 3072            // 3*H*DP
#define M_ROWS 4096         // B*N

// Scratch (no allocations allowed)
__device__ float g_qkv [(size_t)M_ROWS * EQ_];   // 48 MB (tf32-rounded)
__device__ float g_attn[(size_t)M_ROWS * D_];    // 16 MB (tf32-rounded)
__device__ float g_xr  [(size_t)M_ROWS * D_];    // 16 MB x, tf32-rounded
__device__ float g_wq  [(size_t)D_ * EQ_];       // 12 MB W_qkv, tf32-rounded
__device__ float g_wo  [(size_t)D_ * D_];        //  4 MB W_out, tf32-rounded

// ---------------------------------------------------------------------------
// Helpers
// ---------------------------------------------------------------------------
__device__ __forceinline__ uint32_t smem_u32(const void* p) {
    uint32_t a;
    asm("{ .reg .u64 t; cvta.to.shared.u64 t, %1; cvt.u32.u64 %0, t; }"
        : "=r"(a) : "l"(p));
    return a;
}

__device__ __forceinline__ uint32_t f2tf(float x) {
    uint32_t r;
    asm("cvt.rna.tf32.f32 %0, %1;" : "=r"(r) : "f"(x));
    return r;
}

__device__ __forceinline__ void cp16(uint32_t dst, const float* src) {
    asm volatile("cp.async.cg.shared.global [%0], [%1], 16;"
                 :: "r"(dst), "l"(__cvta_generic_to_global(src)));
}
#define CP_COMMIT asm volatile("cp.async.commit_group;" ::: "memory")
#define CP_WAIT0  asm volatile("cp.async.wait_group 0;" ::: "memory")
#define CP_WAIT1  asm volatile("cp.async.wait_group 1;" ::: "memory")

// D += A(16x8 tf32, row) * B(8x8 tf32, col)
__device__ __forceinline__ void mma8(float d[4], const uint32_t a[4], const uint32_t b[2]) {
    asm volatile(
        "mma.sync.aligned.m16n8k8.row.col.f32.tf32.tf32.f32 "
        "{%0,%1,%2,%3}, {%4,%5,%6,%7}, {%8,%9}, {%0,%1,%2,%3};"
        : "+f"(d[0]), "+f"(d[1]), "+f"(d[2]), "+f"(d[3])
        : "r"(a[0]), "r"(a[1]), "r"(a[2]), "r"(a[3]), "r"(b[0]), "r"(b[1]));
}

// ---------------------------------------------------------------------------
// Pre-round f32 -> tf32 bit patterns (elementwise, float4)
// ---------------------------------------------------------------------------
__global__ __launch_bounds__(256) void round_tf32_kernel(
    const float4* __restrict__ in, float4* __restrict__ out, int n4)
{
    int i = blockIdx.x * blockDim.x + threadIdx.x;
    if (i >= n4) return;
    float4 v = in[i];
    uint4 u;
    u.x = f2tf(v.x); u.y = f2tf(v.y); u.z = f2tf(v.z); u.w = f2tf(v.w);
    *(uint4*)&out[i] = u;
}

// ---------------------------------------------------------------------------
// GEMM: C[M,Nn] = A[M,K] @ B[K,Nn] + bias (row-major, operands pre-tf32)
// CTA 128x128, KC=32, 8 warps (2x4) of 64x32, 3-stage cp.async, 1 sync/chunk.
// ---------------------------------------------------------------------------
#define AST 4608   // A stage stride in words
#define BST 4352   // B stage stride in words
#define GEMM_SMEM (3*18432 + 3*17408)

template<bool ROUND_OUT>
__global__ __launch_bounds__(256, 2) void gemm_tc(
    const float* __restrict__ A, const float* __restrict__ Bw,
    const float* __restrict__ bias, float* __restrict__ C,
    int M, int Nn, int K)
{
    extern __shared__ char smem[];
    const uint32_t sA0 = smem_u32(smem);
    const uint32_t sB0 = sA0 + 3 * 18432;
    const uint32_t* uA = (const uint32_t*)smem;
    const uint32_t* uB = (const uint32_t*)(smem + 3 * 18432);

    const int tid = threadIdx.x;
    const int wid = tid >> 5, lane = tid & 31;
    const int gid = lane >> 2, tig = lane & 3;
    const int wm = wid >> 2, wn = wid & 3;
    const int m0 = blockIdx.y * 128, n0 = blockIdx.x * 128;

    float acc[4][4][4];
#pragma unroll
    for (int i = 0; i < 4; i++)
#pragma unroll
        for (int j = 0; j < 4; j++)
#pragma unroll
            for (int r = 0; r < 4; r++) acc[i][j][r] = 0.f;

    auto load_chunk = [&](int k0, int s) {
        const uint32_t da = sA0 + s * (AST * 4);
        const uint32_t db = sB0 + s * (BST * 4);
#pragma unroll
        for (int p = 0; p < 4; p++) {
            int idx = tid + p * 256;
            int m = idx >> 3, k4 = (idx & 7) * 4;
            cp16(da + (m * 36 + k4) * 4, A + (size_t)(m0 + m) * K + k0 + k4);
        }
#pragma unroll
        for (int p = 0; p < 4; p++) {
            int idx = tid + p * 256;
            int kr = idx >> 5, n4 = (idx & 31) * 4;
            cp16(db + (kr * 136 + n4) * 4, Bw + (size_t)(k0 + kr) * Nn + n0 + n4);
        }
        CP_COMMIT;
    };

    const int nch = K >> 5;
    load_chunk(0, 0);
    if (nch > 1) load_chunk(32, 1);

    int stage = 0;
    for (int c = 0; c < nch; c++) {
        if (c + 1 < nch) { CP_WAIT1; } else { CP_WAIT0; }
        __syncthreads();
        if (c + 2 < nch) {
            int s2 = stage + 2; if (s2 >= 3) s2 -= 3;
            load_chunk((c + 2) * 32, s2);
        }

        const uint32_t* cA = uA + stage * AST;
        const uint32_t* cB = uB + stage * BST;

#pragma unroll
        for (int kk = 0; kk < 4; kk++) {
            const int k = kk * 8;
            uint32_t af[4][4], bf[4][2];
#pragma unroll
            for (int mt = 0; mt < 4; mt++) {
                const uint32_t* pr = cA + (wm * 64 + mt * 16 + gid) * 36 + k + tig;
                af[mt][0] = pr[0];
                af[mt][1] = pr[8 * 36];
                af[mt][2] = pr[4];
                af[mt][3] = pr[8 * 36 + 4];
            }
#pragma unroll
            for (int nt = 0; nt < 4; nt++) {
                const uint32_t* pc = cB + (k + tig) * 136 + wn * 32 + nt * 8 + gid;
                bf[nt][0] = pc[0];
                bf[nt][1] = pc[4 * 136];
            }
#pragma unroll
            for (int mt = 0; mt < 4; mt++)
#pragma unroll
                for (int nt = 0; nt < 4; nt++)
                    mma8(acc[mt][nt], af[mt], bf[nt]);
        }
        stage++; if (stage >= 3) stage -= 3;
    }

    // epilogue
#pragma unroll
    for (int mt = 0; mt < 4; mt++) {
        const int row = m0 + wm * 64 + mt * 16 + gid;
#pragma unroll
        for (int nt = 0; nt < 4; nt++) {
            const int col = n0 + wn * 32 + nt * 8 + 2 * tig;
            float2 bv = *(const float2*)(bias + col);
            float v00 = acc[mt][nt][0] + bv.x, v01 = acc[mt][nt][1] + bv.y;
            float v10 = acc[mt][nt][2] + bv.x, v11 = acc[mt][nt][3] + bv.y;
            if (ROUND_OUT) {
                uint2 u0; u0.x = f2tf(v00); u0.y = f2tf(v01);
                uint2 u1; u1.x = f2tf(v10); u1.y = f2tf(v11);
                *(uint2*)(C + (size_t)row * Nn + col) = u0;
                *(uint2*)(C + (size_t)(row + 8) * Nn + col) = u1;
            } else {
                float2 o0; o0.x = v00; o0.y = v01;
                float2 o1; o1.x = v10; o1.y = v11;
                *(float2*)(C + (size_t)row * Nn + col) = o0;
                *(float2*)(C + (size_t)(row + 8) * Nn + col) = o1;
            }
        }
    }
}

// ---------------------------------------------------------------------------
// Flash attention (tf32 mma.sync, pre-rounded qkv): CTA = (b,h,128-q tile),
// 8 warps x 16 query rows, 2 CTAs/SM. K/V 2-stage cp.async, 1 sync/tile.
// P never touches smem: PV A-fragments built from S fragments via quad shfl.
// smem: Q [128][68] @0 | K 2x[64][68] | V 2x[64][72]   = 106496 B
// ---------------------------------------------------------------------------
#define KST 4352   // K stage words
#define VST 4608   // V stage words
#define FLASH_SMEM (34816 + 2*17408 + 2*18432)

__global__ __launch_bounds__(256, 2) void flash_tc(
    const float* __restrict__ qkv, float* __restrict__ attn)
{
    extern __shared__ char smem[];
    const uint32_t* uQ = (const uint32_t*)smem;
    const uint32_t* uK = (const uint32_t*)(smem + 34816);
    const uint32_t* uV = (const uint32_t*)(smem + 34816 + 2 * 17408);
    const uint32_t sQ = smem_u32(smem);
    const uint32_t sK = sQ + 34816;
    const uint32_t sV = sK + 2 * 17408;

    const int tid = threadIdx.x, wid = tid >> 5, lane = tid & 31;
    const int gid = lane >> 2, tig = lane & 3;
    const int qt = blockIdx.x, h = blockIdx.y, b = blockIdx.z;
    const size_t rowbase = (size_t)(b * N_) * EQ_ + h * 192;
    const int q0 = qt * 128;

    auto load_kv = [&](int t, int s) {
#pragma unroll
        for (int p = 0; p < 4; p++) {
            int idx = tid + p * 256;
            int r = idx >> 4, c4 = (idx & 15) * 4;
            const float* g = qkv + rowbase + (size_t)(t * 64 + r) * EQ_;
            cp16(sK + s * 17408 + (r * 68 + c4) * 4, g + 64 + c4);
            cp16(sV + s * 18432 + (r * 72 + c4) * 4, g + 128 + c4);
        }
        CP_COMMIT;
    };

    // prologue: Q shares commit group with KV tile 0
#pragma unroll
    for (int p = 0; p < 8; p++) {
        int idx = tid + p * 256;
        int r = idx >> 4, c4 = (idx & 15) * 4;
        cp16(sQ + (r * 68 + c4) * 4, qkv + rowbase + (size_t)(q0 + r) * EQ_ + c4);
    }
    load_kv(0, 0);

    uint32_t qf[8][4];
    float o[8][4];
#pragma unroll
    for (int nt = 0; nt < 8; nt++)
#pragma unroll
        for (int r = 0; r < 4; r++) o[nt][r] = 0.f;
    float m0r = -1e30f, m1r = -1e30f, l0r = 0.f, l1r = 0.f;

    const int srcA = (lane & ~3) | (tig >> 1);   // quad source for P cols tig
    const int srcB = srcA + 2;                   // quad source for P cols tig+4
    const bool odd = (tig & 1);

    const int T = N_ / 64;
    for (int t = 0; t < T; t++) {
        CP_WAIT0;
        __syncthreads();
        if (t + 1 < T) load_kv(t + 1, (t + 1) & 1);

        if (t == 0) {
            // persistent Q fragments (pre-rounded tf32 bits; *0.125 keeps tf32)
#pragma unroll
            for (int kk = 0; kk < 8; kk++) {
                const uint32_t* pr = uQ + (wid * 16 + gid) * 68 + kk * 8 + tig;
                qf[kk][0] = __float_as_uint(__uint_as_float(pr[0]) * 0.125f);
                qf[kk][1] = __float_as_uint(__uint_as_float(pr[8 * 68]) * 0.125f);
                qf[kk][2] = __float_as_uint(__uint_as_float(pr[4]) * 0.125f);
                qf[kk][3] = __float_as_uint(__uint_as_float(pr[8 * 68 + 4]) * 0.125f);
            }
        }
        const uint32_t* cK = uK + (t & 1) * KST;
        const uint32_t* cV = uV + (t & 1) * VST;

        // S = Q @ K^T (warp: 16 x 64)
        float sc[8][4];
#pragma unroll
        for (int nt = 0; nt < 8; nt++)
#pragma unroll
            for (int r = 0; r < 4; r++) sc[nt][r] = 0.f;
#pragma unroll
        for (int kk = 0; kk < 8; kk++) {
#pragma unroll
            for (int nt = 0; nt < 8; nt++) {
                uint32_t bf[2];
                const uint32_t* pc = cK + (nt * 8 + gid) * 68 + kk * 8 + tig;
                bf[0] = pc[0];
                bf[1] = pc[4];
                mma8(sc[nt], qf[kk], bf);
            }
        }

        // online softmax (rows gid, gid+8; reduce over 4-lane quad)
        float mx0 = sc[0][0], mx1 = sc[0][2];
#pragma unroll
        for (int nt = 0; nt < 8; nt++) {
            mx0 = fmaxf(mx0, fmaxf(sc[nt][0], sc[nt][1]));
            mx1 = fmaxf(mx1, fmaxf(sc[nt][2], sc[nt][3]));
        }
        mx0 = fmaxf(mx0, __shfl_xor_sync(0xffffffffu, mx0, 1));
        mx0 = fmaxf(mx0, __shfl_xor_sync(0xffffffffu, mx0, 2));
        mx1 = fmaxf(mx1, __shfl_xor_sync(0xffffffffu, mx1, 1));
        mx1 = fmaxf(mx1, __shfl_xor_sync(0xffffffffu, mx1, 2));

        const float mn0 = fmaxf(m0r, mx0), mn1 = fmaxf(m1r, mx1);
        const float scl0 = __expf(m0r - mn0), scl1 = __expf(m1r - mn1);
        m0r = mn0; m1r = mn1;

        float sum0 = 0.f, sum1 = 0.f;
#pragma unroll
        for (int nt = 0; nt < 8; nt++) {
            sc[nt][0] = __expf(sc[nt][0] - mn0); sum0 += sc[nt][0];
            sc[nt][1] = __expf(sc[nt][1] - mn0); sum0 += sc[nt][1];
            sc[nt][2] = __expf(sc[nt][2] - mn1); sum1 += sc[nt][2];
            sc[nt][3] = __expf(sc[nt][3] - mn1); sum1 += sc[nt][3];
        }
        l0r = l0r * scl0 + sum0;
        l1r = l1r * scl1 + sum1;
#pragma unroll
        for (int nt = 0; nt < 8; nt++) {
            o[nt][0] *= scl0; o[nt][1] *= scl0;
            o[nt][2] *= scl1; o[nt][3] *= scl1;
        }

        // O += P @ V ; PV A-fragments built from sc via quad shuffles.
        // P[row gid][col c]: owner lane (gid*4 + c/2), reg (c&1) [rows gid]
        // or 2+(c&1) [rows gid+8]. Need cols tig, tig+4 per kk-block.
#pragma unroll
        for (int kk = 0; kk < 8; kk++) {
            uint32_t p0 = f2tf(sc[kk][0]), p1 = f2tf(sc[kk][1]);
            uint32_t p2 = f2tf(sc[kk][2]), p3 = f2tf(sc[kk][3]);
            uint32_t s0a = __shfl_sync(0xffffffffu, p0, srcA);
            uint32_t s1a = __shfl_sync(0xffffffffu, p1, srcA);
            uint32_t s2a = __shfl_sync(0xffffffffu, p2, srcA);
            uint32_t s3a = __shfl_sync(0xffffffffu, p3, srcA);
            uint32_t s0b = __shfl_sync(0xffffffffu, p0, srcB);
            uint32_t s1b = __shfl_sync(0xffffffffu, p1, srcB);
            uint32_t s2b = __shfl_sync(0xffffffffu, p2, srcB);
            uint32_t s3b = __shfl_sync(0xffffffffu, p3, srcB);
            uint32_t af[4];
            af[0] = odd ? s1a : s0a;
            af[1] = odd ? s3a : s2a;
            af[2] = odd ? s1b : s0b;
            af[3] = odd ? s3b : s2b;
#pragma unroll
            for (int nt = 0; nt < 8; nt++) {
                uint32_t bf[2];
                const uint32_t* pv = cV + (kk * 8 + tig) * 72 + nt * 8 + gid;
                bf[0] = pv[0];
                bf[1] = pv[4 * 72];
                mma8(o[nt], af, bf);
            }
        }
    }

    // finalize (write tf32-rounded so gemm3 loads raw bits)
    l0r += __shfl_xor_sync(0xffffffffu, l0r, 1);
    l0r += __shfl_xor_sync(0xffffffffu, l0r, 2);
    l1r += __shfl_xor_sync(0xffffffffu, l1r, 1);
    l1r += __shfl_xor_sync(0xffffffffu, l1r, 2);
    const float inv0 = 1.0f / l0r, inv1 = 1.0f / l1r;

    const int q = b * N_ + q0 + wid * 16 + gid;
    uint32_t* or0 = (uint32_t*)attn + (size_t)q * D_ + h * 64 + 2 * tig;
    uint32_t* or1 = (uint32_t*)attn + (size_t)(q + 8) * D_ + h * 64 + 2 * tig;
#pragma unroll
    for (int nt = 0; nt < 8; nt++) {
        uint2 v0; v0.x = f2tf(o[nt][0] * inv0); v0.y = f2tf(o[nt][1] * inv0);
        uint2 v1; v1.x = f2tf(o[nt][2] * inv1); v1.y = f2tf(o[nt][3] * inv1);
        *(uint2*)(or0 + nt * 8) = v0;
        *(uint2*)(or1 + nt * 8) = v1;
    }
}

// ---------------------------------------------------------------------------
// Launch
// ---------------------------------------------------------------------------
extern "C" void kernel_launch(void* const* d_in, const int* in_sizes, int n_in,
                              void* d_out, int out_size)
{
    const float* x     = (const float*)d_in[0];
    const float* W_qkv = (const float*)d_in[1];
    const float* b_qkv = (const float*)d_in[2];
    const float* W_out = (const float*)d_in[3];
    const float* b_out = (const float*)d_in[4];
    float* out = (float*)d_out;

    float *qkv, *attn, *xr, *wq, *wo;
    cudaGetSymbolAddress((void**)&qkv,  g_qkv);
    cudaGetSymbolAddress((void**)&attn, g_attn);
    cudaGetSymbolAddress((void**)&xr,   g_xr);
    cudaGetSymbolAddress((void**)&wq,   g_wq);
    cudaGetSymbolAddress((void**)&wo,   g_wo);

    cudaFuncSetAttribute(gemm_tc<true>,  cudaFuncAttributeMaxDynamicSharedMemorySize, GEMM_SMEM);
    cudaFuncSetAttribute(gemm_tc<false>, cudaFuncAttributeMaxDynamicSharedMemorySize, GEMM_SMEM);
    cudaFuncSetAttribute(flash_tc, cudaFuncAttributeMaxDynamicSharedMemorySize, FLASH_SMEM);

    // 0) pre-round operands to tf32 bit patterns
    {
        int n4;
        n4 = (M_ROWS * D_) / 4;
        round_tf32_kernel<<<(n4 + 255) / 256, 256>>>((const float4*)x, (float4*)xr, n4);
        n4 = (D_ * EQ_) / 4;
        round_tf32_kernel<<<(n4 + 255) / 256, 256>>>((const float4*)W_qkv, (float4*)wq, n4);
        n4 = (D_ * D_) / 4;
        round_tf32_kernel<<<(n4 + 255) / 256, 256>>>((const float4*)W_out, (float4*)wo, n4);
    }

    // 1) QKV projection (output tf32-rounded for flash)
    gemm_tc<true><<<dim3(EQ_ / 128, M_ROWS / 128), 256, GEMM_SMEM>>>(
        xr, wq, b_qkv, qkv, M_ROWS, EQ_, D_);

    // 2) fused flash attention -> attn (tf32-rounded)
    flash_tc<<<dim3(N_ / 128, H_, B_), 256, FLASH_SMEM>>>(qkv, attn);

    // 3) output projection (full f32 out)
    gemm_tc<false><<<dim3(D_ / 128, M_ROWS / 128), 256, GEMM_SMEM>>>(
        attn, wo, b_out, out, M_ROWS, D_, D_);
}

// round 7
// speedup vs baseline: 1.2278x; 1.1317x over previous
#include <cuda_runtime.h>
#include <cstdint>
#include <cstddef>

// Problem constants
#define B_  2
#define N_  2048
#define D_  1024
#define H_  16
#define DP_ 64
#define EQ_ 3072            // 3*H*DP
#define M_ROWS 4096         // B*N

// Scratch (no allocations allowed)
__device__ float g_qkv [(size_t)M_ROWS * EQ_];   // 48 MB (tf32-rounded)
__device__ float g_attn[(size_t)M_ROWS * D_];    // 16 MB (tf32-rounded)
__device__ float g_xr  [(size_t)M_ROWS * D_];    // 16 MB x, tf32-rounded
__device__ float g_wq  [(size_t)D_ * EQ_];       // 12 MB W_qkv, tf32-rounded
__device__ float g_wo  [(size_t)D_ * D_];        //  4 MB W_out, tf32-rounded

// ---------------------------------------------------------------------------
// Helpers
// ---------------------------------------------------------------------------
__device__ __forceinline__ uint32_t smem_u32(const void* p) {
    uint32_t a;
    asm("{ .reg .u64 t; cvta.to.shared.u64 t, %1; cvt.u32.u64 %0, t; }"
        : "=r"(a) : "l"(p));
    return a;
}

__device__ __forceinline__ uint32_t f2tf(float x) {
    uint32_t r;
    asm("cvt.rna.tf32.f32 %0, %1;" : "=r"(r) : "f"(x));
    return r;
}

__device__ __forceinline__ void cp16(uint32_t dst, const float* src) {
    asm volatile("cp.async.cg.shared.global [%0], [%1], 16;"
                 :: "r"(dst), "l"(__cvta_generic_to_global(src)));
}
#define CP_COMMIT asm volatile("cp.async.commit_group;" ::: "memory")
#define CP_WAIT0  asm volatile("cp.async.wait_group 0;" ::: "memory")
#define CP_WAIT1  asm volatile("cp.async.wait_group 1;" ::: "memory")

// D += A(16x8 tf32, row) * B(8x8 tf32, col)
__device__ __forceinline__ void mma8(float d[4], const uint32_t a[4], const uint32_t b[2]) {
    asm volatile(
        "mma.sync.aligned.m16n8k8.row.col.f32.tf32.tf32.f32 "
        "{%0,%1,%2,%3}, {%4,%5,%6,%7}, {%8,%9}, {%0,%1,%2,%3};"
        : "+f"(d[0]), "+f"(d[1]), "+f"(d[2]), "+f"(d[3])
        : "r"(a[0]), "r"(a[1]), "r"(a[2]), "r"(a[3]), "r"(b[0]), "r"(b[1]));
}

// ---------------------------------------------------------------------------
// Pre-round f32 -> tf32 bit patterns (elementwise, float4)
// ---------------------------------------------------------------------------
__global__ __launch_bounds__(256) void round_tf32_kernel(
    const float4* __restrict__ in, float4* __restrict__ out, int n4)
{
    int i = blockIdx.x * blockDim.x + threadIdx.x;
    if (i >= n4) return;
    float4 v = in[i];
    uint4 u;
    u.x = f2tf(v.x); u.y = f2tf(v.y); u.z = f2tf(v.z); u.w = f2tf(v.w);
    *(uint4*)&out[i] = u;
}

// ---------------------------------------------------------------------------
// GEMM: C[M,Nn] = A[M,K] @ B[K,Nn] + bias (row-major, operands pre-tf32)
// CTA 128x128, 128 threads: 4 warps (2x2) of 64x64. KC=32, 3-stage cp.async.
// smem stages: A [128][36] (18432B), B [32][136] (17408B)
// ---------------------------------------------------------------------------
#define AST 4608   // A stage stride in words
#define BST 4352   // B stage stride in words
#define GEMM_SMEM (3*18432 + 3*17408)

template<bool ROUND_OUT>
__global__ __launch_bounds__(128, 2) void gemm_tc(
    const float* __restrict__ A, const float* __restrict__ Bw,
    const float* __restrict__ bias, float* __restrict__ C,
    int M, int Nn, int K)
{
    extern __shared__ char smem[];
    const uint32_t sA0 = smem_u32(smem);
    const uint32_t sB0 = sA0 + 3 * 18432;
    const uint32_t* uA = (const uint32_t*)smem;
    const uint32_t* uB = (const uint32_t*)(smem + 3 * 18432);

    const int tid = threadIdx.x;
    const int wid = tid >> 5, lane = tid & 31;
    const int gid = lane >> 2, tig = lane & 3;
    const int wm = wid >> 1, wn = wid & 1;
    const int m0 = blockIdx.y * 128, n0 = blockIdx.x * 128;

    float acc[4][8][4];
#pragma unroll
    for (int i = 0; i < 4; i++)
#pragma unroll
        for (int j = 0; j < 8; j++)
#pragma unroll
            for (int r = 0; r < 4; r++) acc[i][j][r] = 0.f;

    auto load_chunk = [&](int k0, int s) {
        const uint32_t da = sA0 + s * (AST * 4);
        const uint32_t db = sB0 + s * (BST * 4);
#pragma unroll
        for (int p = 0; p < 8; p++) {
            int idx = tid + p * 128;
            int m = idx >> 3, k4 = (idx & 7) * 4;
            cp16(da + (m * 36 + k4) * 4, A + (size_t)(m0 + m) * K + k0 + k4);
        }
#pragma unroll
        for (int p = 0; p < 8; p++) {
            int idx = tid + p * 128;
            int kr = idx >> 5, n4 = (idx & 31) * 4;
            cp16(db + (kr * 136 + n4) * 4, Bw + (size_t)(k0 + kr) * Nn + n0 + n4);
        }
        CP_COMMIT;
    };

    const int nch = K >> 5;
    load_chunk(0, 0);
    if (nch > 1) load_chunk(32, 1);

    int stage = 0;
    for (int c = 0; c < nch; c++) {
        if (c + 1 < nch) { CP_WAIT1; } else { CP_WAIT0; }
        __syncthreads();
        if (c + 2 < nch) {
            int s2 = stage + 2; if (s2 >= 3) s2 -= 3;
            load_chunk((c + 2) * 32, s2);
        }

        const uint32_t* cA = uA + stage * AST;
        const uint32_t* cB = uB + stage * BST;

#pragma unroll
        for (int kk = 0; kk < 4; kk++) {
            const int k = kk * 8;
            uint32_t af[4][4], bf[8][2];
#pragma unroll
            for (int mt = 0; mt < 4; mt++) {
                const uint32_t* pr = cA + (wm * 64 + mt * 16 + gid) * 36 + k + tig;
                af[mt][0] = pr[0];
                af[mt][1] = pr[8 * 36];
                af[mt][2] = pr[4];
                af[mt][3] = pr[8 * 36 + 4];
            }
#pragma unroll
            for (int nt = 0; nt < 8; nt++) {
                const uint32_t* pc = cB + (k + tig) * 136 + wn * 64 + nt * 8 + gid;
                bf[nt][0] = pc[0];
                bf[nt][1] = pc[4 * 136];
            }
#pragma unroll
            for (int mt = 0; mt < 4; mt++)
#pragma unroll
                for (int nt = 0; nt < 8; nt++)
                    mma8(acc[mt][nt], af[mt], bf[nt]);
        }
        stage++; if (stage >= 3) stage -= 3;
    }

    // epilogue
#pragma unroll
    for (int mt = 0; mt < 4; mt++) {
        const int row = m0 + wm * 64 + mt * 16 + gid;
#pragma unroll
        for (int nt = 0; nt < 8; nt++) {
            const int col = n0 + wn * 64 + nt * 8 + 2 * tig;
            float2 bv = *(const float2*)(bias + col);
            float v00 = acc[mt][nt][0] + bv.x, v01 = acc[mt][nt][1] + bv.y;
            float v10 = acc[mt][nt][2] + bv.x, v11 = acc[mt][nt][3] + bv.y;
            if (ROUND_OUT) {
                uint2 u0; u0.x = f2tf(v00); u0.y = f2tf(v01);
                uint2 u1; u1.x = f2tf(v10); u1.y = f2tf(v11);
                *(uint2*)(C + (size_t)row * Nn + col) = u0;
                *(uint2*)(C + (size_t)(row + 8) * Nn + col) = u1;
            } else {
                float2 o0; o0.x = v00; o0.y = v01;
                float2 o1; o1.x = v10; o1.y = v11;
                *(float2*)(C + (size_t)row * Nn + col) = o0;
                *(float2*)(C + (size_t)(row + 8) * Nn + col) = o1;
            }
        }
    }
}

// ---------------------------------------------------------------------------
// Flash attention: CTA = (b,h,128-q tile), 128 threads = 4 warps x 32 query
// rows (2 row-groups of 16). K/V fragments loaded once per kk, reused by both
// groups. 2-stage cp.async, 2 CTAs/SM. P stays in registers (quad shfl).
// smem: Q [128][68] @0 | K 2x[64][68] | V 2x[64][72]   = 106496 B
// ---------------------------------------------------------------------------
#define KST 4352   // K stage words
#define VST 4608   // V stage words
#define FLASH_SMEM (34816 + 2*17408 + 2*18432)

__global__ __launch_bounds__(128, 2) void flash_tc(
    const float* __restrict__ qkv, float* __restrict__ attn)
{
    extern __shared__ char smem[];
    const uint32_t* uQ = (const uint32_t*)smem;
    const uint32_t* uK = (const uint32_t*)(smem + 34816);
    const uint32_t* uV = (const uint32_t*)(smem + 34816 + 2 * 17408);
    const uint32_t sQ = smem_u32(smem);
    const uint32_t sK = sQ + 34816;
    const uint32_t sV = sK + 2 * 17408;

    const int tid = threadIdx.x, wid = tid >> 5, lane = tid & 31;
    const int gid = lane >> 2, tig = lane & 3;
    const int qt = blockIdx.x, h = blockIdx.y, b = blockIdx.z;
    const size_t rowbase = (size_t)(b * N_) * EQ_ + h * 192;
    const int q0 = qt * 128;
    const int wr = wid * 32;              // warp's first query row in tile

    auto load_kv = [&](int t, int s) {
#pragma unroll
        for (int p = 0; p < 8; p++) {
            int idx = tid + p * 128;
            int r = idx >> 4, c4 = (idx & 15) * 4;
            const float* g = qkv + rowbase + (size_t)(t * 64 + r) * EQ_;
            cp16(sK + s * 17408 + (r * 68 + c4) * 4, g + 64 + c4);
            cp16(sV + s * 18432 + (r * 72 + c4) * 4, g + 128 + c4);
        }
        CP_COMMIT;
    };

    // prologue: Q shares commit group with KV tile 0
#pragma unroll
    for (int p = 0; p < 16; p++) {
        int idx = tid + p * 128;
        int r = idx >> 4, c4 = (idx & 15) * 4;
        cp16(sQ + (r * 68 + c4) * 4, qkv + rowbase + (size_t)(q0 + r) * EQ_ + c4);
    }
    load_kv(0, 0);

    uint32_t qf[2][8][4];
    float o[2][8][4];
#pragma unroll
    for (int g = 0; g < 2; g++)
#pragma unroll
        for (int nt = 0; nt < 8; nt++)
#pragma unroll
            for (int r = 0; r < 4; r++) o[g][nt][r] = 0.f;
    float mr[2][2] = {{-1e30f, -1e30f}, {-1e30f, -1e30f}};
    float lr[2][2] = {{0.f, 0.f}, {0.f, 0.f}};

    const int srcA = (lane & ~3) | (tig >> 1);   // quad source for P cols tig
    const int srcB = srcA + 2;                   // quad source for P cols tig+4
    const bool odd = (tig & 1);

    const int T = N_ / 64;
    for (int t = 0; t < T; t++) {
        CP_WAIT0;
        __syncthreads();
        if (t + 1 < T) load_kv(t + 1, (t + 1) & 1);

        if (t == 0) {
            // persistent Q fragments (pre-rounded tf32; *0.125 stays tf32)
#pragma unroll
            for (int g = 0; g < 2; g++)
#pragma unroll
                for (int kk = 0; kk < 8; kk++) {
                    const uint32_t* pr = uQ + (wr + g * 16 + gid) * 68 + kk * 8 + tig;
                    qf[g][kk][0] = __float_as_uint(__uint_as_float(pr[0]) * 0.125f);
                    qf[g][kk][1] = __float_as_uint(__uint_as_float(pr[8 * 68]) * 0.125f);
                    qf[g][kk][2] = __float_as_uint(__uint_as_float(pr[4]) * 0.125f);
                    qf[g][kk][3] = __float_as_uint(__uint_as_float(pr[8 * 68 + 4]) * 0.125f);
                }
        }
        const uint32_t* cK = uK + (t & 1) * KST;
        const uint32_t* cV = uV + (t & 1) * VST;

        // S = Q @ K^T (warp: 32 x 64); K-frags loaded once, used by 2 groups
        float sc[2][8][4];
#pragma unroll
        for (int g = 0; g < 2; g++)
#pragma unroll
            for (int nt = 0; nt < 8; nt++)
#pragma unroll
                for (int r = 0; r < 4; r++) sc[g][nt][r] = 0.f;
#pragma unroll
        for (int kk = 0; kk < 8; kk++) {
            uint32_t bf[8][2];
#pragma unroll
            for (int nt = 0; nt < 8; nt++) {
                const uint32_t* pc = cK + (nt * 8 + gid) * 68 + kk * 8 + tig;
                bf[nt][0] = pc[0];
                bf[nt][1] = pc[4];
            }
#pragma unroll
            for (int g = 0; g < 2; g++)
#pragma unroll
                for (int nt = 0; nt < 8; nt++)
                    mma8(sc[g][nt], qf[g][kk], bf[nt]);
        }

        // online softmax per group (rows gid, gid+8; quad reduce)
        float scl[2][2];
#pragma unroll
        for (int g = 0; g < 2; g++) {
            float mx0 = sc[g][0][0], mx1 = sc[g][0][2];
#pragma unroll
            for (int nt = 0; nt < 8; nt++) {
                mx0 = fmaxf(mx0, fmaxf(sc[g][nt][0], sc[g][nt][1]));
                mx1 = fmaxf(mx1, fmaxf(sc[g][nt][2], sc[g][nt][3]));
            }
            mx0 = fmaxf(mx0, __shfl_xor_sync(0xffffffffu, mx0, 1));
            mx0 = fmaxf(mx0, __shfl_xor_sync(0xffffffffu, mx0, 2));
            mx1 = fmaxf(mx1, __shfl_xor_sync(0xffffffffu, mx1, 1));
            mx1 = fmaxf(mx1, __shfl_xor_sync(0xffffffffu, mx1, 2));

            const float mn0 = fmaxf(mr[g][0], mx0), mn1 = fmaxf(mr[g][1], mx1);
            scl[g][0] = __expf(mr[g][0] - mn0);
            scl[g][1] = __expf(mr[g][1] - mn1);
            mr[g][0] = mn0; mr[g][1] = mn1;

            float sum0 = 0.f, sum1 = 0.f;
#pragma unroll
            for (int nt = 0; nt < 8; nt++) {
                sc[g][nt][0] = __expf(sc[g][nt][0] - mn0); sum0 += sc[g][nt][0];
                sc[g][nt][1] = __expf(sc[g][nt][1] - mn0); sum0 += sc[g][nt][1];
                sc[g][nt][2] = __expf(sc[g][nt][2] - mn1); sum1 += sc[g][nt][2];
                sc[g][nt][3] = __expf(sc[g][nt][3] - mn1); sum1 += sc[g][nt][3];
            }
            lr[g][0] = lr[g][0] * scl[g][0] + sum0;
            lr[g][1] = lr[g][1] * scl[g][1] + sum1;
#pragma unroll
            for (int nt = 0; nt < 8; nt++) {
                o[g][nt][0] *= scl[g][0]; o[g][nt][1] *= scl[g][0];
                o[g][nt][2] *= scl[g][1]; o[g][nt][3] *= scl[g][1];
            }
        }

        // O += P @ V ; V-frags loaded once per kk, P frags via quad shuffles
#pragma unroll
        for (int kk = 0; kk < 8; kk++) {
            uint32_t vf[8][2];
#pragma unroll
            for (int nt = 0; nt < 8; nt++) {
                const uint32_t* pv = cV + (kk * 8 + tig) * 72 + nt * 8 + gid;
                vf[nt][0] = pv[0];
                vf[nt][1] = pv[4 * 72];
            }
#pragma unroll
            for (int g = 0; g < 2; g++) {
                uint32_t p0 = f2tf(sc[g][kk][0]), p1 = f2tf(sc[g][kk][1]);
                uint32_t p2 = f2tf(sc[g][kk][2]), p3 = f2tf(sc[g][kk][3]);
                uint32_t s0a = __shfl_sync(0xffffffffu, p0, srcA);
                uint32_t s1a = __shfl_sync(0xffffffffu, p1, srcA);
                uint32_t s2a = __shfl_sync(0xffffffffu, p2, srcA);
                uint32_t s3a = __shfl_sync(0xffffffffu, p3, srcA);
                uint32_t s0b = __shfl_sync(0xffffffffu, p0, srcB);
                uint32_t s1b = __shfl_sync(0xffffffffu, p1, srcB);
                uint32_t s2b = __shfl_sync(0xffffffffu, p2, srcB);
                uint32_t s3b = __shfl_sync(0xffffffffu, p3, srcB);
                uint32_t af[4];
                af[0] = odd ? s1a : s0a;
                af[1] = odd ? s3a : s2a;
                af[2] = odd ? s1b : s0b;
                af[3] = odd ? s3b : s2b;
#pragma unroll
                for (int nt = 0; nt < 8; nt++)
                    mma8(o[g][nt], af, vf[nt]);
            }
        }
    }

    // finalize (write tf32-rounded so gemm3 loads raw bits)
#pragma unroll
    for (int g = 0; g < 2; g++) {
        float l0 = lr[g][0], l1 = lr[g][1];
        l0 += __shfl_xor_sync(0xffffffffu, l0, 1);
        l0 += __shfl_xor_sync(0xffffffffu, l0, 2);
        l1 += __shfl_xor_sync(0xffffffffu, l1, 1);
        l1 += __shfl_xor_sync(0xffffffffu, l1, 2);
        const float inv0 = 1.0f / l0, inv1 = 1.0f / l1;

        const int q = b * N_ + q0 + wr + g * 16 + gid;
        uint32_t* or0 = (uint32_t*)attn + (size_t)q * D_ + h * 64 + 2 * tig;
        uint32_t* or1 = (uint32_t*)attn + (size_t)(q + 8) * D_ + h * 64 + 2 * tig;
#pragma unroll
        for (int nt = 0; nt < 8; nt++) {
            uint2 v0; v0.x = f2tf(o[g][nt][0] * inv0); v0.y = f2tf(o[g][nt][1] * inv0);
            uint2 v1; v1.x = f2tf(o[g][nt][2] * inv1); v1.y = f2tf(o[g][nt][3] * inv1);
            *(uint2*)(or0 + nt * 8) = v0;
            *(uint2*)(or1 + nt * 8) = v1;
        }
    }
}

// ---------------------------------------------------------------------------
// Launch
// ---------------------------------------------------------------------------
extern "C" void kernel_launch(void* const* d_in, const int* in_sizes, int n_in,
                              void* d_out, int out_size)
{
    const float* x     = (const float*)d_in[0];
    const float* W_qkv = (const float*)d_in[1];
    const float* b_qkv = (const float*)d_in[2];
    const float* W_out = (const float*)d_in[3];
    const float* b_out = (const float*)d_in[4];
    float* out = (float*)d_out;

    float *qkv, *attn, *xr, *wq, *wo;
    cudaGetSymbolAddress((void**)&qkv,  g_qkv);
    cudaGetSymbolAddress((void**)&attn, g_attn);
    cudaGetSymbolAddress((void**)&xr,   g_xr);
    cudaGetSymbolAddress((void**)&wq,   g_wq);
    cudaGetSymbolAddress((void**)&wo,   g_wo);

    cudaFuncSetAttribute(gemm_tc<true>,  cudaFuncAttributeMaxDynamicSharedMemorySize, GEMM_SMEM);
    cudaFuncSetAttribute(gemm_tc<false>, cudaFuncAttributeMaxDynamicSharedMemorySize, GEMM_SMEM);
    cudaFuncSetAttribute(flash_tc, cudaFuncAttributeMaxDynamicSharedMemorySize, FLASH_SMEM);
    cudaFuncSetAttribute(gemm_tc<true>,  cudaFuncAttributePreferredSharedMemoryCarveout, 100);
    cudaFuncSetAttribute(gemm_tc<false>, cudaFuncAttributePreferredSharedMemoryCarveout, 100);
    cudaFuncSetAttribute(flash_tc, cudaFuncAttributePreferredSharedMemoryCarveout, 100);

    // 0) pre-round operands to tf32 bit patterns
    {
        int n4;
        n4 = (M_ROWS * D_) / 4;
        round_tf32_kernel<<<(n4 + 255) / 256, 256>>>((const float4*)x, (float4*)xr, n4);
        n4 = (D_ * EQ_) / 4;
        round_tf32_kernel<<<(n4 + 255) / 256, 256>>>((const float4*)W_qkv, (float4*)wq, n4);
        n4 = (D_ * D_) / 4;
        round_tf32_kernel<<<(n4 + 255) / 256, 256>>>((const float4*)W_out, (float4*)wo, n4);
    }

    // 1) QKV projection (output tf32-rounded for flash)
    gemm_tc<true><<<dim3(EQ_ / 128, M_ROWS / 128), 128, GEMM_SMEM>>>(
        xr, wq, b_qkv, qkv, M_ROWS, EQ_, D_);

    // 2) fused flash attention -> attn (tf32-rounded)
    flash_tc<<<dim3(N_ / 128, H_, B_), 128, FLASH_SMEM>>>(qkv, attn);

    // 3) output projection (full f32 out)
    gemm_tc<false><<<dim3(D_ / 128, M_ROWS / 128), 128, GEMM_SMEM>>>(
        attn, wo, b_out, out, M_ROWS, D_, D_);
}